// round 17
// baseline (speedup 1.0000x reference)
#include <cuda_runtime.h>
#include <cstdint>
#include <cstddef>

#define BATCH   4
#define NNODE   4096
#define DF      128
#define UNITS   128
#define TILE_R  128
#define SC      128                 // s rows per chunk
#define NCHUNK  (NNODE / SC)        // 32
#define ADJ_STRIDE 132              // floats per adj smem row: 128 + 4 pad (528 B)
#define ADJ_ST_FLOATS (SC * ADJ_STRIDE)   // 16896 floats / buffer
#define ZS      132                 // zsm row stride

// Combined weights (device scratch; no cudaMalloc allowed)
//   g_Wap[p*256 + 2*c + e] = Wa[2p+e][c]   (pair p = k/2, e = k&1)
__device__ float g_Wap[DF * UNITS];  // W1 + Wr@W2, pair-interleaved
__device__ float g_Wbp[DF * UNITS];  // Ws@W2, pair-interleaved
__device__ float g_Wr2[DF * UNITS];  // Wr@W2 row-major (deg==0 fixup only)

// ---------------------------------------------------------------------------
// Phase 0: weight prep. 128 blocks x 128 threads. Block i computes row i.
// ---------------------------------------------------------------------------
__global__ void prep_weights(const float* __restrict__ Wmsg,
                             const float* __restrict__ Wupd) {
    __shared__ float ws[DF];
    __shared__ float wr[DF];
    const int i = blockIdx.x;
    const int j = threadIdx.x;
    ws[j] = Wmsg[i * UNITS + j];
    wr[j] = Wmsg[(DF + i) * UNITS + j];
    __syncthreads();
    float sa = 0.f, sr = 0.f;
#pragma unroll 4
    for (int k = 0; k < DF; ++k) {
        const float w2 = Wupd[(DF + k) * UNITS + j];
        sa = fmaf(ws[k], w2, sa);
        sr = fmaf(wr[k], w2, sr);
    }
    const int pidx = (i >> 1) * 256 + (j << 1) + (i & 1);
    g_Wbp[pidx] = sa;
    g_Wr2[i * UNITS + j] = sr;
    g_Wap[pidx] = Wupd[i * UNITS + j] + sr;
}

// Packed f32x2 FMA: d = a*b + d  (both lanes)
__device__ __forceinline__ void fma2(unsigned long long& d, unsigned long long a,
                                     unsigned long long b) {
    asm("fma.rn.f32x2 %0, %1, %2, %0;" : "+l"(d) : "l"(a), "l"(b));
}

// ---------------------------------------------------------------------------
// Main fused kernel. grid (32, 4), 1024 threads, 1 CTA/SM.
// dynamic smem: 2 adj buffers of SC*132 floats = 135,168 B
// phase-2 overlay: xsm (stride 128) in buf0, zsm (stride 132) in buf1
// ---------------------------------------------------------------------------
extern __shared__ float smem[];

__global__ __launch_bounds__(1024, 1)
void mpnn_main(const float* __restrict__ x,
               const float* __restrict__ adj,
               float* __restrict__ out) {
    __shared__ float degs[TILE_R];

    const int b   = blockIdx.y;
    const int r0  = blockIdx.x * TILE_R;
    const int tid = threadIdx.x;
    const int w    = tid >> 5;   // warp 0..31: owns r-cols r0+4w .. 4w+3
    const int lane = tid & 31;

    const float* adjb = adj + (size_t)b * NNODE * NNODE;
    const float* xb   = x   + (size_t)b * NNODE * DF;

    // stage chunk c into buf[c&1] via coalesced LDG.128 -> STS.128.
    auto stage = [&](int c) {
        float* dst = smem + (size_t)(c & 1) * ADJ_ST_FLOATS;
        const float* src = adjb + (size_t)c * SC * NNODE + r0;
        const int col = lane << 2;
        const uint4 t0 = *(const uint4*)(src + (size_t)(w      ) * NNODE + col);
        const uint4 t1 = *(const uint4*)(src + (size_t)(w + 32 ) * NNODE + col);
        const uint4 t2 = *(const uint4*)(src + (size_t)(w + 64 ) * NNODE + col);
        const uint4 t3 = *(const uint4*)(src + (size_t)(w + 96 ) * NNODE + col);
        *(uint4*)&dst[(size_t)(w      ) * ADJ_STRIDE + col] = t0;
        *(uint4*)&dst[(size_t)(w + 32 ) * ADJ_STRIDE + col] = t1;
        *(uint4*)&dst[(size_t)(w + 64 ) * ADJ_STRIDE + col] = t2;
        *(uint4*)&dst[(size_t)(w + 96 ) * ADJ_STRIDE + col] = t3;
    };

    float acc[4][4] = {};
    int   dcnt[4]   = {0, 0, 0, 0};

    // -------- phase 1: LDG->STS double-buffered stream + batched-gather scan ----
    stage(0);
    __syncthreads();

    for (int c = 0; c < NCHUNK; ++c) {
        if (c + 1 < NCHUNK) stage(c + 1);   // LDG latency hidden by scan below

        const float* cur = smem + (size_t)(c & 1) * ADJ_ST_FLOATS;
        const int s_chunk = c << 7;

        // 1) all four av vectors (independent LDS)
        float4 av0 = *reinterpret_cast<const float4*>(
            &cur[(      lane) * ADJ_STRIDE + (w << 2)]);
        float4 av1 = *reinterpret_cast<const float4*>(
            &cur[( 32 + lane) * ADJ_STRIDE + (w << 2)]);
        float4 av2 = *reinterpret_cast<const float4*>(
            &cur[( 64 + lane) * ADJ_STRIDE + (w << 2)]);
        float4 av3 = *reinterpret_cast<const float4*>(
            &cur[( 96 + lane) * ADJ_STRIDE + (w << 2)]);

        // 2) 16 ballots -> fused 64-bit masks per r-column (bit p -> s offset p)
        unsigned long long M0a, M1a, M2a, M3a, M0b, M1b, M2b, M3b;
        {
            unsigned a0 = __ballot_sync(0xffffffffu, av0.x != 0.0f);
            unsigned a1 = __ballot_sync(0xffffffffu, av1.x != 0.0f);
            unsigned a2 = __ballot_sync(0xffffffffu, av2.x != 0.0f);
            unsigned a3 = __ballot_sync(0xffffffffu, av3.x != 0.0f);
            M0a = a0 | ((unsigned long long)a1 << 32);
            M0b = a2 | ((unsigned long long)a3 << 32);
            unsigned b0 = __ballot_sync(0xffffffffu, av0.y != 0.0f);
            unsigned b1 = __ballot_sync(0xffffffffu, av1.y != 0.0f);
            unsigned b2 = __ballot_sync(0xffffffffu, av2.y != 0.0f);
            unsigned b3 = __ballot_sync(0xffffffffu, av3.y != 0.0f);
            M1a = b0 | ((unsigned long long)b1 << 32);
            M1b = b2 | ((unsigned long long)b3 << 32);
            unsigned c0 = __ballot_sync(0xffffffffu, av0.z != 0.0f);
            unsigned c1 = __ballot_sync(0xffffffffu, av1.z != 0.0f);
            unsigned c2 = __ballot_sync(0xffffffffu, av2.z != 0.0f);
            unsigned c3 = __ballot_sync(0xffffffffu, av3.z != 0.0f);
            M2a = c0 | ((unsigned long long)c1 << 32);
            M2b = c2 | ((unsigned long long)c3 << 32);
            unsigned d0 = __ballot_sync(0xffffffffu, av0.w != 0.0f);
            unsigned d1 = __ballot_sync(0xffffffffu, av1.w != 0.0f);
            unsigned d2 = __ballot_sync(0xffffffffu, av2.w != 0.0f);
            unsigned d3 = __ballot_sync(0xffffffffu, av3.w != 0.0f);
            M3a = d0 | ((unsigned long long)d1 << 32);
            M3b = d2 | ((unsigned long long)d3 << 32);
        }
        dcnt[0] += __popcll(M0a) + __popcll(M0b);
        dcnt[1] += __popcll(M1a) + __popcll(M1b);
        dcnt[2] += __popcll(M2a) + __popcll(M2b);
        dcnt[3] += __popcll(M3a) + __popcll(M3b);

        // 3) joint walk: one bit from EACH nonzero mask per iteration
        //    -> up to 4 independent LDG.128 in flight (MLP=4)
#define JOINT_WALK(MM0, MM1, MM2, MM3, SOFF)                                         \
        {                                                                            \
            const float* xw = xb + (size_t)(s_chunk + (SOFF)) * DF + (lane << 2);    \
            while (MM0 | MM1 | MM2 | MM3) {                                          \
                const bool h0 = MM0 != 0, h1 = MM1 != 0,                             \
                           h2 = MM2 != 0, h3 = MM3 != 0;                             \
                const int i0 = __ffsll(MM0) - 1;                                     \
                const int i1 = __ffsll(MM1) - 1;                                     \
                const int i2 = __ffsll(MM2) - 1;                                     \
                const int i3 = __ffsll(MM3) - 1;                                     \
                float4 v0, v1, v2, v3;                                               \
                if (h0) v0 = *(const float4*)(xw + (size_t)i0 * DF);                 \
                if (h1) v1 = *(const float4*)(xw + (size_t)i1 * DF);                 \
                if (h2) v2 = *(const float4*)(xw + (size_t)i2 * DF);                 \
                if (h3) v3 = *(const float4*)(xw + (size_t)i3 * DF);                 \
                if (h0) { acc[0][0] += v0.x; acc[0][1] += v0.y;                      \
                          acc[0][2] += v0.z; acc[0][3] += v0.w; MM0 &= MM0 - 1; }    \
                if (h1) { acc[1][0] += v1.x; acc[1][1] += v1.y;                      \
                          acc[1][2] += v1.z; acc[1][3] += v1.w; MM1 &= MM1 - 1; }    \
                if (h2) { acc[2][0] += v2.x; acc[2][1] += v2.y;                      \
                          acc[2][2] += v2.z; acc[2][3] += v2.w; MM2 &= MM2 - 1; }    \
                if (h3) { acc[3][0] += v3.x; acc[3][1] += v3.y;                      \
                          acc[3][2] += v3.z; acc[3][3] += v3.w; MM3 &= MM3 - 1; }    \
            }                                                                        \
        }
        JOINT_WALK(M0a, M1a, M2a, M3a, 0)
        JOINT_WALK(M0b, M1b, M2b, M3b, 64)
#undef JOINT_WALK

        __syncthreads();   // scan of buf[c&1] and stage of buf[(c+1)&1] complete
    }

    // -------- phase boundary: overlay smem with xsm (buf0) / zsm (buf1) --------
    float* xsm = smem;                        // [128][128]
    float* zsm = smem + ADJ_ST_FLOATS;        // [128][132]

    // stage this block's own x rows: same coalesced LDG->STS pattern
    {
        const float* src = xb + (size_t)r0 * DF;
        const int col = lane << 2;
        const uint4 t0 = *(const uint4*)(src + (size_t)(w      ) * DF + col);
        const uint4 t1 = *(const uint4*)(src + (size_t)(w + 32 ) * DF + col);
        const uint4 t2 = *(const uint4*)(src + (size_t)(w + 64 ) * DF + col);
        const uint4 t3 = *(const uint4*)(src + (size_t)(w + 96 ) * DF + col);
        *(uint4*)&xsm[(size_t)(w      ) * DF + col] = t0;
        *(uint4*)&xsm[(size_t)(w + 32 ) * DF + col] = t1;
        *(uint4*)&xsm[(size_t)(w + 64 ) * DF + col] = t2;
        *(uint4*)&xsm[(size_t)(w + 96 ) * DF + col] = t3;
    }

    // dcnt is warp-uniform (popc of full ballots)
#pragma unroll
    for (int rp = 0; rp < 4; ++rp) {
        const int r = (w << 2) + rp;
        const float d = (float)dcnt[rp];
        const float inv = (dcnt[rp] > 0) ? (1.0f / d) : 0.0f;
        float4 zv;
        zv.x = acc[rp][0] * inv; zv.y = acc[rp][1] * inv;
        zv.z = acc[rp][2] * inv; zv.w = acc[rp][3] * inv;
        *reinterpret_cast<float4*>(&zsm[(size_t)r * ZS + (lane << 2)]) = zv;
        if (lane == 0) degs[r] = d;
    }
    __syncthreads();

    // -------- phase 2: out = xsm @ Wa + zsm @ Wb  (k-pair packed f32x2) --------
    const int rg  = w >> 2;                 // 0..7 -> rows 16*rg .. +16
    const int col = ((w & 3) << 5) + lane;  // 0..127

    unsigned long long cacc[16];
#pragma unroll
    for (int i = 0; i < 16; ++i) cacc[i] = 0ull;

#pragma unroll 1
    for (int pass = 0; pass < 2; ++pass) {
        const float* A  = pass ? zsm : xsm;
        const int    As = pass ? ZS : DF;
        const float* Wp = pass ? g_Wbp : g_Wap;
#pragma unroll 4
        for (int k = 0; k < DF; k += 4) {
            const unsigned long long w0 = *reinterpret_cast<const unsigned long long*>(
                &Wp[(size_t)(k >> 1) * 256 + (col << 1)]);
            const unsigned long long w1 = *reinterpret_cast<const unsigned long long*>(
                &Wp[(size_t)((k >> 1) + 1) * 256 + (col << 1)]);
#pragma unroll
            for (int i = 0; i < 16; ++i) {
                const ulonglong2 av = *reinterpret_cast<const ulonglong2*>(
                    &A[(size_t)(16 * rg + i) * As + k]);   // warp-uniform broadcast
                fma2(cacc[i], av.x, w0);
                fma2(cacc[i], av.y, w1);
            }
        }
    }

    float* outb = out + ((size_t)b * NNODE + r0) * UNITS;
#pragma unroll
    for (int i = 0; i < 16; ++i) {
        const int r = 16 * rg + i;
        unsigned lo, hi;
        asm("mov.b64 {%0, %1}, %2;" : "=r"(lo), "=r"(hi) : "l"(cacc[i]));
        float o = __uint_as_float(lo) + __uint_as_float(hi);

        if (degs[r] == 0.0f) {
            // message term must be exactly zero: remove the x@Wr@W2 contribution
            float corr = 0.0f;
            for (int k = 0; k < DF; ++k)
                corr = fmaf(xsm[(size_t)r * DF + k], g_Wr2[k * UNITS + col], corr);
            o -= corr;
        }
        outb[(size_t)r * UNITS + col] = o;
    }
}

// ---------------------------------------------------------------------------
// Launch
// ---------------------------------------------------------------------------
extern "C" void kernel_launch(void* const* d_in, const int* in_sizes, int n_in,
                              void* d_out, int out_size) {
    (void)in_sizes; (void)n_in; (void)out_size;
    const float* x    = (const float*)d_in[0];
    const float* adj  = (const float*)d_in[1];
    const float* Wmsg = (const float*)d_in[2];
    const float* Wupd = (const float*)d_in[3];
    float* out = (float*)d_out;

    prep_weights<<<128, 128>>>(Wmsg, Wupd);

    const size_t shbytes = (size_t)2 * ADJ_ST_FLOATS * sizeof(float);  // 135168
    cudaFuncSetAttribute(mpnn_main, cudaFuncAttributeMaxDynamicSharedMemorySize,
                         (int)shbytes);
    mpnn_main<<<dim3(NNODE / TILE_R, BATCH), 1024, shbytes>>>(x, adj, out);
}